// round 4
// baseline (speedup 1.0000x reference)
#include <cuda_runtime.h>

#define BB 2
#define CC 3
#define DD 128
#define HH 128
#define WW 128
#define NSEG 11                      // 11 non-uniform h-segments (9-10 rows)
#define NWARPS (BB * DD * NSEG)      // 2816 warp tasks
#define NTHREADS 128
#define WPB (NTHREADS / 32)          // 4 warps/block
#define NBLOCKS (NWARPS / WPB)       // 704 blocks  (<= 740 = 5/SM * 148: ONE wave)

#define W_GRAD 0.1f
#define W_TV 0.002f
#define W_BG 0.15

// 9 partial sums:
// 0:mask 1:mx 2:my 3:mz 4:(mae+mse) 5:bg 6:gtx 7:gty 8:gtz
#define NSUMS 9
__device__ double g_sums[NSUMS];
__device__ unsigned int g_count;

__device__ __forceinline__ float warp_sum(float v) {
#pragma unroll
    for (int o = 16; o; o >>= 1) v += __shfl_down_sync(0xffffffffu, v, o);
    return v;
}

__global__ __launch_bounds__(NTHREADS)
void loss_kernel(const float4* __restrict__ pred,
                 const float4* __restrict__ targ,
                 const float4* __restrict__ mask,
                 float* __restrict__ out) {
    const int wid  = threadIdx.x >> 5;
    const int lane = threadIdx.x & 31;
    const int gwarp = blockIdx.x * WPB + wid;

    // task decode: gwarp -> (b, d, seg)   (seg via const division -> mul.hi)
    const int seg = gwarp % NSEG;
    const int bd  = gwarp / NSEG;
    const int d   = bd & (DD - 1);
    const int b   = bd >> 7;             // / DD
    const int h0  = (seg * HH) / NSEG;
    const int h1  = ((seg + 1) * HH) / NSEG;

    const float dv  = (d < DD - 1) ? 1.0f : 0.0f;     // dx validity
    const float ze  = (lane < 31) ? 1.0f : 0.0f;      // w=127 edge

    const int ROWQ = WW / 4;                          // 32 float4 per row
    const int CSTR = DD * HH * ROWQ;                  // channel stride (float4)
    // d+1 plane offset (clamped at last plane -> 0, masked by dv anyway)
    const int dskip = (d < DD - 1) ? HH * ROWQ : 0;

    int mo = ((b * DD + d) * HH + h0) * ROWQ + lane;
    int po = (((b * CC) * DD + d) * HH + h0) * ROWQ + lane;

    // previous-h state (diff = (p-t)*m, pin = p*m). Zero prev mask kills
    // the h0==0 boundary terms automatically (min(m,0)=0).
    float4 pm = make_float4(0.f, 0.f, 0.f, 0.f);
    float4 pdf[CC], ppi[CC];
#pragma unroll
    for (int c = 0; c < CC; c++) {
        pdf[c] = make_float4(0.f, 0.f, 0.f, 0.f);
        ppi[c] = make_float4(0.f, 0.f, 0.f, 0.f);
    }

    if (h0 > 0) {  // preload row h0-1 to seed the y-gradient
        pm = mask[mo - ROWQ];
#pragma unroll
        for (int c = 0; c < CC; c++) {
            float4 p = pred[po + c * CSTR - ROWQ];
            float4 t = targ[po + c * CSTR - ROWQ];
            pdf[c] = make_float4((p.x - t.x) * pm.x, (p.y - t.y) * pm.y,
                                 (p.z - t.z) * pm.z, (p.w - t.w) * pm.w);
            ppi[c] = make_float4(p.x * pm.x, p.y * pm.y, p.z * pm.z, p.w * pm.w);
        }
    }

    float s_m = 0.f, s_mx = 0.f, s_my = 0.f, s_mz = 0.f;
    float s_mm = 0.f, s_bg = 0.f;
    float s_gtx = 0.f, s_gty = 0.f, s_gtz = 0.f;

    for (int hh = h0; hh < h1; hh++) {
        const float4 m  = mask[mo];
        const float4 md = mask[mo + dskip];

        const float4 mx4 = make_float4(fminf(m.x, md.x) * dv, fminf(m.y, md.y) * dv,
                                       fminf(m.z, md.z) * dv, fminf(m.w, md.w) * dv);
        const float4 my4 = make_float4(fminf(m.x, pm.x), fminf(m.y, pm.y),
                                       fminf(m.z, pm.z), fminf(m.w, pm.w));
        const float mnx = __shfl_down_sync(0xffffffffu, m.x, 1);
        const float mz0 = fminf(m.x, m.y), mz1 = fminf(m.y, m.z);
        const float mz2 = fminf(m.z, m.w), mz3 = fminf(m.w, mnx) * ze;

        s_m  += (m.x + m.y) + (m.z + m.w);
        s_mx += (mx4.x + mx4.y) + (mx4.z + mx4.w);
        s_my += (my4.x + my4.y) + (my4.z + my4.w);
        s_mz += (mz0 + mz1) + (mz2 + mz3);

#pragma unroll
        for (int c = 0; c < CC; c++) {
            const float4 p  = pred[po + c * CSTR];
            const float4 t  = targ[po + c * CSTR];
            const float4 pd = pred[po + c * CSTR + dskip];
            const float4 td = targ[po + c * CSTR + dskip];

            const float4 df = make_float4((p.x - t.x) * m.x, (p.y - t.y) * m.y,
                                          (p.z - t.z) * m.z, (p.w - t.w) * m.w);
            const float4 pi = make_float4(p.x * m.x, p.y * m.y, p.z * m.z, p.w * m.w);
            const float4 dfd = make_float4((pd.x - td.x) * md.x, (pd.y - td.y) * md.y,
                                           (pd.z - td.z) * md.z, (pd.w - td.w) * md.w);
            const float4 pid = make_float4(pd.x * md.x, pd.y * md.y,
                                           pd.z * md.z, pd.w * md.w);

            // mae + mse share the same denominator -> one accumulator
            s_mm += fabsf(df.x) + df.x * df.x + fabsf(df.y) + df.y * df.y
                  + fabsf(df.z) + df.z * df.z + fabsf(df.w) + df.w * df.w;
            s_bg += fabsf(p.x) * (1.f - m.x) + fabsf(p.y) * (1.f - m.y)
                  + fabsf(p.z) * (1.f - m.z) + fabsf(p.w) * (1.f - m.w);

            // grad (w=0.1) + tv (w=0.002) share denominators -> fold weights in
            s_gtx += (W_GRAD * fabsf(dfd.x - df.x) + W_TV * fabsf(pid.x - pi.x)) * mx4.x
                   + (W_GRAD * fabsf(dfd.y - df.y) + W_TV * fabsf(pid.y - pi.y)) * mx4.y
                   + (W_GRAD * fabsf(dfd.z - df.z) + W_TV * fabsf(pid.z - pi.z)) * mx4.z
                   + (W_GRAD * fabsf(dfd.w - df.w) + W_TV * fabsf(pid.w - pi.w)) * mx4.w;

            s_gty += (W_GRAD * fabsf(df.x - pdf[c].x) + W_TV * fabsf(pi.x - ppi[c].x)) * my4.x
                   + (W_GRAD * fabsf(df.y - pdf[c].y) + W_TV * fabsf(pi.y - ppi[c].y)) * my4.y
                   + (W_GRAD * fabsf(df.z - pdf[c].z) + W_TV * fabsf(pi.z - ppi[c].z)) * my4.z
                   + (W_GRAD * fabsf(df.w - pdf[c].w) + W_TV * fabsf(pi.w - ppi[c].w)) * my4.w;

            const float dnx = __shfl_down_sync(0xffffffffu, df.x, 1);
            const float pnx = __shfl_down_sync(0xffffffffu, pi.x, 1);
            s_gtz += (W_GRAD * fabsf(df.y - df.x) + W_TV * fabsf(pi.y - pi.x)) * mz0
                   + (W_GRAD * fabsf(df.z - df.y) + W_TV * fabsf(pi.z - pi.y)) * mz1
                   + (W_GRAD * fabsf(df.w - df.z) + W_TV * fabsf(pi.w - pi.z)) * mz2
                   + (W_GRAD * fabsf(dnx - df.w) + W_TV * fabsf(pnx - pi.w)) * mz3;

            pdf[c] = df;
            ppi[c] = pi;
        }
        pm = m;
        mo += ROWQ; po += ROWQ;
    }

    // ---- block-level reduction: warp -> smem -> NSUMS atomics per block ----
    __shared__ float red[WPB][NSUMS];
    float vals[NSUMS] = {s_m, s_mx, s_my, s_mz, s_mm, s_bg, s_gtx, s_gty, s_gtz};
#pragma unroll
    for (int i = 0; i < NSUMS; i++) {
        const float r = warp_sum(vals[i]);
        if (lane == 0) red[wid][i] = r;
    }
    __syncthreads();

    if (threadIdx.x < NSUMS) {
        float acc = red[0][threadIdx.x];
#pragma unroll
        for (int w = 1; w < WPB; w++) acc += red[w][threadIdx.x];
        atomicAdd(&g_sums[threadIdx.x], (double)acc);
        __threadfence();
    }
    __syncthreads();

    // ---- last block finalizes + resets scratch (graph-replay determinism) ----
    if (threadIdx.x == 0) {
        const unsigned int old = atomicAdd(&g_count, 1u);
        if (old == NBLOCKS - 1) {
            double s[NSUMS];
#pragma unroll
            for (int i = 0; i < NSUMS; i++) s[i] = atomicAdd(&g_sums[i], 0.0);
            const double e = 1e-8;
            const double sm  = s[0], smx = s[1], smy = s[2], smz = s[3];
            const double mm  = s[4], bg  = s[5];
            const double gtx = s[6], gty = s[7], gtz = s[8];
            const double inv = (double)BB * DD * HH * WW - sm;

            const double r = mm / (sm * 3.0 + e)          // mae + mse
                           + gtx / (smx * 3.0 + e)
                           + gty / (smy * 3.0 + e)
                           + gtz / (smz * 3.0 + e)
                           + W_BG * (bg / (inv * 3.0 + e));
            out[0] = (float)r;

#pragma unroll
            for (int i = 0; i < NSUMS; i++) g_sums[i] = 0.0;
            g_count = 0u;
        }
    }
}

extern "C" void kernel_launch(void* const* d_in, const int* in_sizes, int n_in,
                              void* d_out, int out_size) {
    // mask is the smallest input; pred/target keep their relative order
    int mi = 0;
    for (int i = 1; i < n_in; i++)
        if (in_sizes[i] < in_sizes[mi]) mi = i;
    int others[2], k = 0;
    for (int i = 0; i < 3; i++)
        if (i != mi) others[k++] = i;

    const float4* pred = (const float4*)d_in[others[0]];
    const float4* targ = (const float4*)d_in[others[1]];
    const float4* mask = (const float4*)d_in[mi];

    loss_kernel<<<NBLOCKS, NTHREADS>>>(pred, targ, mask, (float*)d_out);
}

// round 5
// speedup vs baseline: 1.4698x; 1.4698x over previous
#include <cuda_runtime.h>

#define BB 2
#define CC 3
#define DD 128
#define HH 128
#define WW 128
#define NSEG 11                      // 11 non-uniform h-segments (9-10 rows)
#define NWARPS (BB * DD * NSEG)      // 2816 warp tasks
#define NTHREADS 128
#define WPB (NTHREADS / 32)          // 4 warps/block
#define NBLOCKS (NWARPS / WPB)       // 704 blocks  (<= 740 = 5/SM * 148: ONE wave)

#define W_GRAD 0.1f
#define W_TV 0.002f
#define W_BG 0.15

// 9 partial sums:
// 0:mask 1:mx 2:my 3:mz 4:(mae+mse) 5:bg 6:gtx 7:gty 8:gtz
#define NSUMS 9
__device__ double g_sums[NSUMS];
__device__ unsigned int g_count;

__device__ __forceinline__ float warp_sum(float v) {
#pragma unroll
    for (int o = 16; o; o >>= 1) v += __shfl_down_sync(0xffffffffu, v, o);
    return v;
}

__global__ __launch_bounds__(NTHREADS, 5)   // pin 5 blocks/SM -> regs <= 102
void loss_kernel(const float4* __restrict__ pred,
                 const float4* __restrict__ targ,
                 const float4* __restrict__ mask,
                 float* __restrict__ out) {
    const int wid  = threadIdx.x >> 5;
    const int lane = threadIdx.x & 31;
    const int gwarp = blockIdx.x * WPB + wid;

    // task decode: gwarp -> (b, d, seg)   (seg via const division -> mul.hi)
    const int seg = gwarp % NSEG;
    const int bd  = gwarp / NSEG;
    const int d   = bd & (DD - 1);
    const int b   = bd >> 7;             // / DD
    const int h0  = (seg * HH) / NSEG;
    const int h1  = ((seg + 1) * HH) / NSEG;

    const float dv  = (d < DD - 1) ? 1.0f : 0.0f;     // dx validity
    const float ze  = (lane < 31) ? 1.0f : 0.0f;      // w=127 edge

    const int ROWQ = WW / 4;                          // 32 float4 per row
    const int CSTR = DD * HH * ROWQ;                  // channel stride (float4)
    // d+1 plane offset (clamped at last plane -> 0, masked by dv anyway)
    const int dskip = (d < DD - 1) ? HH * ROWQ : 0;

    int mo = ((b * DD + d) * HH + h0) * ROWQ + lane;
    int po = (((b * CC) * DD + d) * HH + h0) * ROWQ + lane;

    // previous-h state (diff = (p-t)*m, pin = p*m). Zero prev mask kills
    // the h0==0 boundary terms automatically (min(m,0)=0).
    float4 pm = make_float4(0.f, 0.f, 0.f, 0.f);
    float4 pdf[CC], ppi[CC];
#pragma unroll
    for (int c = 0; c < CC; c++) {
        pdf[c] = make_float4(0.f, 0.f, 0.f, 0.f);
        ppi[c] = make_float4(0.f, 0.f, 0.f, 0.f);
    }

    if (h0 > 0) {  // preload row h0-1 to seed the y-gradient
        pm = mask[mo - ROWQ];
#pragma unroll
        for (int c = 0; c < CC; c++) {
            float4 p = pred[po + c * CSTR - ROWQ];
            float4 t = targ[po + c * CSTR - ROWQ];
            pdf[c] = make_float4((p.x - t.x) * pm.x, (p.y - t.y) * pm.y,
                                 (p.z - t.z) * pm.z, (p.w - t.w) * pm.w);
            ppi[c] = make_float4(p.x * pm.x, p.y * pm.y, p.z * pm.z, p.w * pm.w);
        }
    }

    float s_m = 0.f, s_mx = 0.f, s_my = 0.f, s_mz = 0.f;
    float s_mm = 0.f, s_bg = 0.f;
    float s_gtx = 0.f, s_gty = 0.f, s_gtz = 0.f;

    for (int hh = h0; hh < h1; hh++) {
        const float4 m  = mask[mo];
        const float4 md = mask[mo + dskip];

        const float4 mx4 = make_float4(fminf(m.x, md.x) * dv, fminf(m.y, md.y) * dv,
                                       fminf(m.z, md.z) * dv, fminf(m.w, md.w) * dv);
        const float4 my4 = make_float4(fminf(m.x, pm.x), fminf(m.y, pm.y),
                                       fminf(m.z, pm.z), fminf(m.w, pm.w));
        const float mnx = __shfl_down_sync(0xffffffffu, m.x, 1);
        const float mz0 = fminf(m.x, m.y), mz1 = fminf(m.y, m.z);
        const float mz2 = fminf(m.z, m.w), mz3 = fminf(m.w, mnx) * ze;

        s_m  += (m.x + m.y) + (m.z + m.w);
        s_mx += (mx4.x + mx4.y) + (mx4.z + mx4.w);
        s_my += (my4.x + my4.y) + (my4.z + my4.w);
        s_mz += (mz0 + mz1) + (mz2 + mz3);

#pragma unroll
        for (int c = 0; c < CC; c++) {
            const float4 p  = pred[po + c * CSTR];
            const float4 t  = targ[po + c * CSTR];
            const float4 pd = pred[po + c * CSTR + dskip];
            const float4 td = targ[po + c * CSTR + dskip];

            const float4 df = make_float4((p.x - t.x) * m.x, (p.y - t.y) * m.y,
                                          (p.z - t.z) * m.z, (p.w - t.w) * m.w);
            const float4 pi = make_float4(p.x * m.x, p.y * m.y, p.z * m.z, p.w * m.w);
            const float4 dfd = make_float4((pd.x - td.x) * md.x, (pd.y - td.y) * md.y,
                                           (pd.z - td.z) * md.z, (pd.w - td.w) * md.w);
            const float4 pid = make_float4(pd.x * md.x, pd.y * md.y,
                                           pd.z * md.z, pd.w * md.w);

            // mae + mse share the same denominator -> one accumulator
            s_mm += fabsf(df.x) + df.x * df.x + fabsf(df.y) + df.y * df.y
                  + fabsf(df.z) + df.z * df.z + fabsf(df.w) + df.w * df.w;
            // |p|*(1-m) == |p| - |p*m| for binary m>=0
            s_bg += (fabsf(p.x) - fabsf(pi.x)) + (fabsf(p.y) - fabsf(pi.y))
                  + (fabsf(p.z) - fabsf(pi.z)) + (fabsf(p.w) - fabsf(pi.w));

            // grad (w=0.1) + tv (w=0.002) share denominators -> fold weights in
            s_gtx += (W_GRAD * fabsf(dfd.x - df.x) + W_TV * fabsf(pid.x - pi.x)) * mx4.x
                   + (W_GRAD * fabsf(dfd.y - df.y) + W_TV * fabsf(pid.y - pi.y)) * mx4.y
                   + (W_GRAD * fabsf(dfd.z - df.z) + W_TV * fabsf(pid.z - pi.z)) * mx4.z
                   + (W_GRAD * fabsf(dfd.w - df.w) + W_TV * fabsf(pid.w - pi.w)) * mx4.w;

            s_gty += (W_GRAD * fabsf(df.x - pdf[c].x) + W_TV * fabsf(pi.x - ppi[c].x)) * my4.x
                   + (W_GRAD * fabsf(df.y - pdf[c].y) + W_TV * fabsf(pi.y - ppi[c].y)) * my4.y
                   + (W_GRAD * fabsf(df.z - pdf[c].z) + W_TV * fabsf(pi.z - ppi[c].z)) * my4.z
                   + (W_GRAD * fabsf(df.w - pdf[c].w) + W_TV * fabsf(pi.w - ppi[c].w)) * my4.w;

            const float dnx = __shfl_down_sync(0xffffffffu, df.x, 1);
            const float pnx = __shfl_down_sync(0xffffffffu, pi.x, 1);
            s_gtz += (W_GRAD * fabsf(df.y - df.x) + W_TV * fabsf(pi.y - pi.x)) * mz0
                   + (W_GRAD * fabsf(df.z - df.y) + W_TV * fabsf(pi.z - pi.y)) * mz1
                   + (W_GRAD * fabsf(df.w - df.z) + W_TV * fabsf(pi.w - pi.z)) * mz2
                   + (W_GRAD * fabsf(dnx - df.w) + W_TV * fabsf(pnx - pi.w)) * mz3;

            pdf[c] = df;
            ppi[c] = pi;
        }
        pm = m;
        mo += ROWQ; po += ROWQ;
    }

    // ---- block-level reduction: warp -> smem -> NSUMS atomics per block ----
    __shared__ float red[WPB][NSUMS];
    float vals[NSUMS] = {s_m, s_mx, s_my, s_mz, s_mm, s_bg, s_gtx, s_gty, s_gtz};
#pragma unroll
    for (int i = 0; i < NSUMS; i++) {
        const float r = warp_sum(vals[i]);
        if (lane == 0) red[wid][i] = r;
    }
    __syncthreads();

    if (threadIdx.x < NSUMS) {
        float acc = red[0][threadIdx.x];
#pragma unroll
        for (int w = 1; w < WPB; w++) acc += red[w][threadIdx.x];
        atomicAdd(&g_sums[threadIdx.x], (double)acc);
        __threadfence();
    }
    __syncthreads();

    // ---- last block finalizes + resets scratch (graph-replay determinism) ----
    if (threadIdx.x == 0) {
        const unsigned int old = atomicAdd(&g_count, 1u);
        if (old == NBLOCKS - 1) {
            double s[NSUMS];
#pragma unroll
            for (int i = 0; i < NSUMS; i++) s[i] = atomicAdd(&g_sums[i], 0.0);
            const double e = 1e-8;
            const double sm  = s[0], smx = s[1], smy = s[2], smz = s[3];
            const double mm  = s[4], bg  = s[5];
            const double gtx = s[6], gty = s[7], gtz = s[8];
            const double inv = (double)BB * DD * HH * WW - sm;

            const double r = mm / (sm * 3.0 + e)          // mae + mse
                           + gtx / (smx * 3.0 + e)
                           + gty / (smy * 3.0 + e)
                           + gtz / (smz * 3.0 + e)
                           + W_BG * (bg / (inv * 3.0 + e));
            out[0] = (float)r;

#pragma unroll
            for (int i = 0; i < NSUMS; i++) g_sums[i] = 0.0;
            g_count = 0u;
        }
    }
}

extern "C" void kernel_launch(void* const* d_in, const int* in_sizes, int n_in,
                              void* d_out, int out_size) {
    // mask is the smallest input; pred/target keep their relative order
    int mi = 0;
    for (int i = 1; i < n_in; i++)
        if (in_sizes[i] < in_sizes[mi]) mi = i;
    int others[2], k = 0;
    for (int i = 0; i < 3; i++)
        if (i != mi) others[k++] = i;

    const float4* pred = (const float4*)d_in[others[0]];
    const float4* targ = (const float4*)d_in[others[1]];
    const float4* mask = (const float4*)d_in[mi];

    loss_kernel<<<NBLOCKS, NTHREADS>>>(pred, targ, mask, (float*)d_out);
}